// round 3
// baseline (speedup 1.0000x reference)
#include <cuda_runtime.h>
#include <cuda_bf16.h>
#include <math_constants.h>

// Problem constants
#define BATCH 64
#define SEQ   256
#define TCH   16
#define VOC   262
#define EMB   64
#define HID   32          // per direction; == warp size
#define G3    96          // 3*HID
#define NSEQ  (BATCH*SEQ) // 16384 words
#define NTASK (NSEQ*2)    // (seq, dir) tasks
#define NJ    16          // HID/2 packed pairs

typedef unsigned long long ull;

// Scratch tables (device globals — no allocation allowed)
__device__ float  g_GIf[VOC * G3];        // bih_f + Wih_f @ emb[c]
__device__ float  g_GIb[VOC * G3];
// Packed recurrent weights: WP[gate][j][lane] = (Whh[gate*32+lane][2j], [2j+1])
__device__ float2 g_WPf[3 * NJ * HID];
__device__ float2 g_WPb[3 * NJ * HID];

__device__ __forceinline__ ull ffma2(ull a, ull b, ull c) {
    ull d;
    asm("fma.rn.f32x2 %0, %1, %2, %3;" : "=l"(d) : "l"(a), "l"(b), "l"(c));
    return d;
}
__device__ __forceinline__ ull pack2(float lo, float hi) {
    ull r;
    asm("mov.b64 %0, {%1, %2};" : "=l"(r) : "f"(lo), "f"(hi));
    return r;
}
__device__ __forceinline__ float pairsum(ull v) {
    float lo, hi;
    asm("mov.b64 {%0, %1}, %2;" : "=f"(lo), "=f"(hi) : "l"(v));
    return lo + hi;
}
__device__ __forceinline__ float sigf(float x) {
    return __fdividef(1.0f, 1.0f + __expf(-x));
}
__device__ __forceinline__ float tanhfast(float x) {
    return fmaf(2.0f, sigf(2.0f * x), -1.0f);
}

// ---------------------------------------------------------------------------
// Kernel 1: build GI lookup tables + packed Whh weight tables
// grid = VOC+1 blocks, 96 threads
// ---------------------------------------------------------------------------
__global__ void build_tables(const float* __restrict__ emb,
                             const float* __restrict__ Wih_f,
                             const float* __restrict__ bih_f,
                             const float* __restrict__ Wih_b,
                             const float* __restrict__ bih_b,
                             const float* __restrict__ Whh_f,
                             const float* __restrict__ Whh_b) {
    int c = blockIdx.x;
    int g = threadIdx.x;  // 0..95
    if (c < VOC) {
        __shared__ float e[EMB];
        if (g < EMB) e[g] = emb[c * EMB + g];
        __syncthreads();
        float af = bih_f[g];
        float ab = bih_b[g];
        #pragma unroll
        for (int k = 0; k < EMB; k++) {
            float ev = e[k];
            af = fmaf(Wih_f[g * EMB + k], ev, af);
            ab = fmaf(Wih_b[g * EMB + k], ev, ab);
        }
        g_GIf[c * G3 + g] = af;
        g_GIb[c * G3 + g] = ab;
    } else {
        // pack Whh into float2 pairs: WP[((gate*NJ)+j)*32 + lane]
        for (int i = g; i < 3 * NJ * HID; i += G3) {
            int gate = i / (NJ * HID);
            int rem  = i % (NJ * HID);
            int j    = rem / HID;
            int lane = rem % HID;
            int row  = gate * HID + lane;
            g_WPf[i] = make_float2(Whh_f[row * HID + 2 * j], Whh_f[row * HID + 2 * j + 1]);
            g_WPb[i] = make_float2(Whh_b[row * HID + 2 * j], Whh_b[row * HID + 2 * j + 1]);
        }
    }
}

// ---------------------------------------------------------------------------
// Kernel 2: persistent-warp bidirectional GRU + temporal max-pool.
// One warp per (sequence, direction). Lane l owns h[l].
// Broadcast via 32 independent SHFLs per step (no smem, no barriers);
// recurrent matvec is 48 packed fma.rn.f32x2 per lane per step.
// ---------------------------------------------------------------------------
__global__ __launch_bounds__(256, 2)
void gru_main(const int* __restrict__ x,
              const float* __restrict__ bhh_f,
              const float* __restrict__ bhh_b,
              float* __restrict__ out) {
    int gtid   = blockIdx.x * blockDim.x + threadIdx.x;
    int w      = gtid >> 5;
    int lane   = gtid & 31;
    int nwarps = (gridDim.x * blockDim.x) >> 5;   // even
    int dir    = w & 1;

    const float*  __restrict__ GI  = dir ? g_GIb : g_GIf;
    const float2* __restrict__ WP  = dir ? g_WPb : g_WPf;
    const float*  __restrict__ bhh = dir ? bhh_b : bhh_f;

    // Per-lane packed recurrent weights (loaded once per persistent warp)
    ull wr[NJ], wz[NJ], wn[NJ];
    #pragma unroll
    for (int j = 0; j < NJ; j++) {
        float2 a = WP[(0 * NJ + j) * HID + lane];
        float2 b = WP[(1 * NJ + j) * HID + lane];
        float2 c = WP[(2 * NJ + j) * HID + lane];
        wr[j] = *(ull*)&a;
        wz[j] = *(ull*)&b;
        wn[j] = *(ull*)&c;
    }
    ull br2 = (ull)__float_as_uint(bhh[lane]);        // bias in lo half
    ull bz2 = (ull)__float_as_uint(bhh[32 + lane]);
    ull bn2 = (ull)__float_as_uint(bhh[64 + lane]);

    for (int task = w; task < NTASK; task += nwarps) {
        int seq = task >> 1;   // task&1 == dir (parity preserved)

        int cm = (lane < TCH) ? x[seq * TCH + lane] : 0;

        float h = 0.0f;
        float hmax = -CUDART_INF_F;

        // prefetch gi for step 0
        int c0 = __shfl_sync(0xffffffffu, cm, dir ? (TCH - 1) : 0);
        const float* gp = GI + c0 * G3 + lane;
        float gir = gp[0], giz = gp[32], gin = gp[64];

        #pragma unroll 1
        for (int tt = 0; tt < TCH; ++tt) {
            // prefetch gi for step tt+1 (last iter: harmless redundant load)
            int tn = (tt + 1) & (TCH - 1);
            int cn = __shfl_sync(0xffffffffu, cm, dir ? (TCH - 1 - tn) : tn);
            const float* gpn = GI + cn * G3 + lane;
            float gir_n = gpn[0], giz_n = gpn[32], gin_n = gpn[64];

            ull ar = br2, az = bz2, an = bn2;
            #pragma unroll
            for (int j = 0; j < NJ; j++) {
                float a = __shfl_sync(0xffffffffu, h, 2 * j);
                float b = __shfl_sync(0xffffffffu, h, 2 * j + 1);
                ull hv = pack2(a, b);
                ar = ffma2(wr[j], hv, ar);
                az = ffma2(wz[j], hv, az);
                an = ffma2(wn[j], hv, an);
            }
            float ghr = pairsum(ar);
            float ghz = pairsum(az);
            float ghn = pairsum(an);

            float r = sigf(gir + ghr);
            float z = sigf(giz + ghz);
            float n = tanhfast(fmaf(r, ghn, gin));
            h = fmaf(z, h - n, n);              // (1-z)*n + z*h
            hmax = fmaxf(hmax, h);

            gir = gir_n; giz = giz_n; gin = gin_n;
        }

        out[seq * (2 * HID) + dir * HID + lane] = hmax;
    }
}

// ---------------------------------------------------------------------------
// kernel_launch
// inputs: x, emb, Wih_f, Whh_f, bih_f, bhh_f, Wih_b, Whh_b, bih_b, bhh_b
// output: float32 [64, 256, 64]
// ---------------------------------------------------------------------------
extern "C" void kernel_launch(void* const* d_in, const int* in_sizes, int n_in,
                              void* d_out, int out_size) {
    const int*   x     = (const int*)  d_in[0];
    const float* emb   = (const float*)d_in[1];
    const float* Wih_f = (const float*)d_in[2];
    const float* Whh_f = (const float*)d_in[3];
    const float* bih_f = (const float*)d_in[4];
    const float* bhh_f = (const float*)d_in[5];
    const float* Wih_b = (const float*)d_in[6];
    const float* Whh_b = (const float*)d_in[7];
    const float* bih_b = (const float*)d_in[8];
    const float* bhh_b = (const float*)d_in[9];
    float* out = (float*)d_out;

    build_tables<<<VOC + 1, G3>>>(emb, Wih_f, bih_f, Wih_b, bih_b, Whh_f, Whh_b);

    // 296 blocks x 256 threads = 2368 persistent warps (2 CTAs/SM @ 128 regs)
    gru_main<<<296, 256>>>(x, bhh_f, bhh_b, out);
}

// round 4
// speedup vs baseline: 1.6803x; 1.6803x over previous
#include <cuda_runtime.h>
#include <cuda_bf16.h>
#include <math_constants.h>

// Problem constants
#define BATCH 64
#define SEQ   256
#define TCH   16
#define VOC   262
#define EMB   64
#define HID   32
#define G3    96
#define NSEQ  (BATCH*SEQ)     // 16384 words
#define NGRP  2048            // (16-seq, dir) groups: 1024 per dir

// Tables (device globals — no allocation allowed)
// g_GI2[dir][c][g] = bih[g] + Wih[g,:]@emb[c] + (g<64 ? bhh[g] : 0)
__device__ float    g_GI2[2 * VOC * G3];
// g_WTt[dir][g][k] = tf32(Whh[g][k]) as raw u32
__device__ unsigned g_WTt[2 * G3 * HID];

__device__ __forceinline__ unsigned tf32_of(float f) {
    unsigned r;
    asm("cvt.rna.tf32.f32 %0, %1;" : "=r"(r) : "f"(f));
    return r;
}
__device__ __forceinline__ void mma_tf32(float d[4], const unsigned a[4],
                                         const unsigned b[2]) {
    asm("mma.sync.aligned.m16n8k8.row.col.f32.tf32.tf32.f32 "
        "{%0,%1,%2,%3}, {%4,%5,%6,%7}, {%8,%9}, {%0,%1,%2,%3};"
        : "+f"(d[0]), "+f"(d[1]), "+f"(d[2]), "+f"(d[3])
        : "r"(a[0]), "r"(a[1]), "r"(a[2]), "r"(a[3]),
          "r"(b[0]), "r"(b[1]));
}
__device__ __forceinline__ float sigf(float x) {
    return __fdividef(1.0f, 1.0f + __expf(-x));
}
__device__ __forceinline__ float tanhfast(float x) {
    return fmaf(2.0f, sigf(2.0f * x), -1.0f);
}

// ---------------------------------------------------------------------------
// Kernel 1: build GI tables (bhh folded for r,z gates) + tf32 Whh copies
// grid = VOC+1, block = 96
// ---------------------------------------------------------------------------
__global__ void build_tables(const float* __restrict__ emb,
                             const float* __restrict__ Wih_f,
                             const float* __restrict__ bih_f,
                             const float* __restrict__ bhh_f,
                             const float* __restrict__ Wih_b,
                             const float* __restrict__ bih_b,
                             const float* __restrict__ bhh_b,
                             const float* __restrict__ Whh_f,
                             const float* __restrict__ Whh_b) {
    int c = blockIdx.x;
    int g = threadIdx.x;  // 0..95
    if (c < VOC) {
        __shared__ float e[EMB];
        if (g < EMB) e[g] = emb[c * EMB + g];
        __syncthreads();
        float af = bih_f[g] + (g < 64 ? bhh_f[g] : 0.0f);
        float ab = bih_b[g] + (g < 64 ? bhh_b[g] : 0.0f);
        #pragma unroll
        for (int k = 0; k < EMB; k++) {
            float ev = e[k];
            af = fmaf(Wih_f[g * EMB + k], ev, af);
            ab = fmaf(Wih_b[g * EMB + k], ev, ab);
        }
        g_GI2[0 * VOC * G3 + c * G3 + g] = af;
        g_GI2[1 * VOC * G3 + c * G3 + g] = ab;
    } else {
        #pragma unroll
        for (int k = 0; k < HID; k++) {
            g_WTt[0 * G3 * HID + g * HID + k] = tf32_of(Whh_f[g * HID + k]);
            g_WTt[1 * G3 * HID + g * HID + k] = tf32_of(Whh_b[g * HID + k]);
        }
    }
}

// ---------------------------------------------------------------------------
// Kernel 2: tensor-core GRU. One warp = 16 sequences, one direction.
// Per step: gh[16,96] = h[16,32] @ WhhT via m16n8k8 tf32 MMAs (2-term
// hi/lo split on h), gi folded in as the C operand, lane-local activations,
// smem-mediated D-layout -> A-layout h exchange.
// ---------------------------------------------------------------------------
__global__ __launch_bounds__(128, 2)
void gru_mma(const int* __restrict__ x,
             const float* __restrict__ bhh_f,
             const float* __restrict__ bhh_b,
             float* __restrict__ out) {
    int w    = blockIdx.x * 4 + (threadIdx.x >> 5);   // 0..2047
    int lane = threadIdx.x & 31;
    int gid  = lane >> 2;     // 0..7  (row group)
    int tig  = lane & 3;      // 0..3  (thread in group)
    int dir  = w >> 10;
    int seq0 = (w & 1023) << 4;

    const float*    __restrict__ GI  = g_GI2 + dir * (VOC * G3);
    const unsigned* __restrict__ WT  = g_WTt + dir * (G3 * HID);
    const float*    __restrict__ bhh = dir ? bhh_b : bhh_f;

    // B fragments (static per warp): bf[nb][kc] = Whh rows 8nb+gid, k 8kc+tig{,+4}
    unsigned bf[12][4][2];
    #pragma unroll
    for (int nb = 0; nb < 12; nb++)
        #pragma unroll
        for (int kc = 0; kc < 4; kc++) {
            const unsigned* p = WT + (8 * nb + gid) * HID + 8 * kc + tig;
            bf[nb][kc][0] = p[0];
            bf[nb][kc][1] = p[4];
        }
    // n-gate recurrent bias (inside the r*(...) factor, so not foldable in GI)
    float bn[4][2];
    #pragma unroll
    for (int hg = 0; hg < 4; hg++) {
        bn[hg][0] = bhh[64 + 8 * hg + 2 * tig];
        bn[hg][1] = bhh[64 + 8 * hg + 2 * tig + 1];
    }

    const int* xA = x + (seq0 + gid) * TCH;
    const int* xB = x + (seq0 + gid + 8) * TCH;

    // h exchange buffers: stride 36 floats -> conflict-free LDS pattern
    __shared__ float sh[4][2][16][36];
    int wb = threadIdx.x >> 5;

    unsigned ahi[4][4], alo[4][4];        // A frags (hi/lo split), h starts at 0
    #pragma unroll
    for (int kc = 0; kc < 4; kc++)
        #pragma unroll
        for (int j = 0; j < 4; j++) { ahi[kc][j] = 0u; alo[kc][j] = 0u; }

    float hn[4][4];     // [hg][slot]; slot: 0=(rowA,c0) 1=(rowA,c1) 2=(rowB,c0) 3=(rowB,c1)
    float hmax[4][4];
    #pragma unroll
    for (int hg = 0; hg < 4; hg++)
        #pragma unroll
        for (int s = 0; s < 4; s++) { hn[hg][s] = 0.0f; hmax[hg][s] = -CUDART_INF_F; }

    int p = 0;
    #pragma unroll 1
    for (int tt = 0; tt < TCH; ++tt) {
        int t  = dir ? (TCH - 1 - tt) : tt;
        int cA = xA[t], cB = xB[t];
        const float* gA = GI + cA * G3;
        const float* gB = GI + cB * G3;

        float2 gr[4][2], gz[4][2], gn[4][2];
        #pragma unroll
        for (int hg = 0; hg < 4; hg++) {
            int o = 8 * hg + 2 * tig;
            gr[hg][0] = *(const float2*)(gA + o);
            gr[hg][1] = *(const float2*)(gB + o);
            gz[hg][0] = *(const float2*)(gA + 32 + o);
            gz[hg][1] = *(const float2*)(gB + 32 + o);
            gn[hg][0] = *(const float2*)(gA + 64 + o);
            gn[hg][1] = *(const float2*)(gB + 64 + o);
        }

        #pragma unroll
        for (int hg = 0; hg < 4; hg++) {
            float dr[4] = {gr[hg][0].x, gr[hg][0].y, gr[hg][1].x, gr[hg][1].y};
            float dz[4] = {gz[hg][0].x, gz[hg][0].y, gz[hg][1].x, gz[hg][1].y};
            float dn[4] = {bn[hg][0],   bn[hg][1],   bn[hg][0],   bn[hg][1]};
            #pragma unroll
            for (int kc = 0; kc < 4; kc++) {
                mma_tf32(dr, ahi[kc], bf[hg][kc]);
                mma_tf32(dz, ahi[kc], bf[hg + 4][kc]);
                mma_tf32(dn, ahi[kc], bf[hg + 8][kc]);
                mma_tf32(dr, alo[kc], bf[hg][kc]);
                mma_tf32(dz, alo[kc], bf[hg + 4][kc]);
                mma_tf32(dn, alo[kc], bf[hg + 8][kc]);
            }
            float gns[4] = {gn[hg][0].x, gn[hg][0].y, gn[hg][1].x, gn[hg][1].y};
            #pragma unroll
            for (int s = 0; s < 4; s++) {
                float r = sigf(dr[s]);
                float z = sigf(dz[s]);
                float n = tanhfast(fmaf(r, dn[s], gns[s]));
                float h = fmaf(z, hn[hg][s] - n, n);   // (1-z)n + z h
                hn[hg][s] = h;
                hmax[hg][s] = fmaxf(hmax[hg][s], h);
            }
        }

        // exchange: D-layout h -> A fragments (hi/lo tf32 split)
        #pragma unroll
        for (int hg = 0; hg < 4; hg++) {
            *(float2*)&sh[wb][p][gid][8 * hg + 2 * tig]     = make_float2(hn[hg][0], hn[hg][1]);
            *(float2*)&sh[wb][p][gid + 8][8 * hg + 2 * tig] = make_float2(hn[hg][2], hn[hg][3]);
        }
        __syncwarp();
        #pragma unroll
        for (int kc = 0; kc < 4; kc++) {
            float r0 = sh[wb][p][gid][8 * kc + tig];
            float r1 = sh[wb][p][gid + 8][8 * kc + tig];
            float r2 = sh[wb][p][gid][8 * kc + tig + 4];
            float r3 = sh[wb][p][gid + 8][8 * kc + tig + 4];
            ahi[kc][0] = tf32_of(r0); alo[kc][0] = __float_as_uint(r0 - __uint_as_float(ahi[kc][0]));
            ahi[kc][1] = tf32_of(r1); alo[kc][1] = __float_as_uint(r1 - __uint_as_float(ahi[kc][1]));
            ahi[kc][2] = tf32_of(r2); alo[kc][2] = __float_as_uint(r2 - __uint_as_float(ahi[kc][2]));
            ahi[kc][3] = tf32_of(r3); alo[kc][3] = __float_as_uint(r3 - __uint_as_float(ahi[kc][3]));
        }
        p ^= 1;
    }

    // write temporal-max output
    int sA = seq0 + gid, sB = seq0 + gid + 8;
    #pragma unroll
    for (int hg = 0; hg < 4; hg++) {
        int col = 8 * hg + 2 * tig;
        *(float2*)(out + sA * 64 + dir * 32 + col) = make_float2(hmax[hg][0], hmax[hg][1]);
        *(float2*)(out + sB * 64 + dir * 32 + col) = make_float2(hmax[hg][2], hmax[hg][3]);
    }
}

// ---------------------------------------------------------------------------
// kernel_launch
// inputs: x, emb, Wih_f, Whh_f, bih_f, bhh_f, Wih_b, Whh_b, bih_b, bhh_b
// output: float32 [64, 256, 64]
// ---------------------------------------------------------------------------
extern "C" void kernel_launch(void* const* d_in, const int* in_sizes, int n_in,
                              void* d_out, int out_size) {
    const int*   x     = (const int*)  d_in[0];
    const float* emb   = (const float*)d_in[1];
    const float* Wih_f = (const float*)d_in[2];
    const float* Whh_f = (const float*)d_in[3];
    const float* bih_f = (const float*)d_in[4];
    const float* bhh_f = (const float*)d_in[5];
    const float* Wih_b = (const float*)d_in[6];
    const float* Whh_b = (const float*)d_in[7];
    const float* bih_b = (const float*)d_in[8];
    const float* bhh_b = (const float*)d_in[9];
    float* out = (float*)d_out;

    build_tables<<<VOC + 1, G3>>>(emb, Wih_f, bih_f, bhh_f,
                                  Wih_b, bih_b, bhh_b, Whh_f, Whh_b);

    // 2048 warps = 512 CTAs x 128 threads; each warp owns 16 seqs, one dir
    gru_mma<<<NGRP / 4, 128>>>(x, bhh_f, bhh_b, out);
}

// round 5
// speedup vs baseline: 2.0783x; 1.2368x over previous
#include <cuda_runtime.h>
#include <cuda_bf16.h>
#include <math_constants.h>

#define BATCH 64
#define SEQ   256
#define TCH   16
#define VOC   262
#define EMB   64
#define HID   32
#define G3    96
#define NSEQ  (BATCH*SEQ)
#define NGRP  2048            // (16-seq, dir) warps

// Tables (device globals — no allocation allowed)
// Permuted GI rows: pos(gate,j) = gate*32 + tig*8 + hg*2 + e  (j = 8hg+2tig+e)
__device__ __align__(128) float g_GI2[2 * VOC * G3];
// Pre-packed tf32 B fragments: [dir][nb][kc][lane] = (W[8nb+gid][8kc+tig], [+4])
__device__ uint2 g_WF[2 * 12 * 4 * 32];

__device__ __forceinline__ unsigned tf32_of(float f) {
    unsigned r;
    asm("cvt.rna.tf32.f32 %0, %1;" : "=r"(r) : "f"(f));
    return r;
}
__device__ __forceinline__ float ex2f(float a) {
    float r;
    asm("ex2.approx.f32 %0, %1;" : "=f"(r) : "f"(a));
    return r;
}
__device__ __forceinline__ float rcpf(float a) {
    float r;
    asm("rcp.approx.f32 %0, %1;" : "=f"(r) : "f"(a));
    return r;
}
__device__ __forceinline__ void mma_tf32(float* d, const unsigned* a,
                                         const unsigned* b) {
    asm("mma.sync.aligned.m16n8k8.row.col.f32.tf32.tf32.f32 "
        "{%0,%1,%2,%3}, {%4,%5,%6,%7}, {%8,%9}, {%0,%1,%2,%3};"
        : "+f"(d[0]), "+f"(d[1]), "+f"(d[2]), "+f"(d[3])
        : "r"(a[0]), "r"(a[1]), "r"(a[2]), "r"(a[3]),
          "r"(b[0]), "r"(b[1]));
}

// ---------------------------------------------------------------------------
// Kernel 1: GI tables (permuted layout, bhh folded for r,z) + B-fragment pack
// grid = VOC+1, block = 192 (tid<96: dir 0, tid>=96: dir 1)
// ---------------------------------------------------------------------------
__global__ void build_tables(const float* __restrict__ emb,
                             const float* __restrict__ Wih_f,
                             const float* __restrict__ bih_f,
                             const float* __restrict__ bhh_f,
                             const float* __restrict__ Wih_b,
                             const float* __restrict__ bih_b,
                             const float* __restrict__ bhh_b,
                             const float* __restrict__ Whh_f,
                             const float* __restrict__ Whh_b) {
    int c   = blockIdx.x;
    int tid = threadIdx.x;
    if (c < VOC) {
        int dir = tid / 96;
        int g   = tid % 96;
        __shared__ float e[EMB];
        if (tid < EMB) e[tid] = emb[c * EMB + tid];
        __syncthreads();
        const float* Wih = dir ? Wih_b : Wih_f;
        const float* bih = dir ? bih_b : bih_f;
        const float* bhh = dir ? bhh_b : bhh_f;
        float a0 = bih[g] + (g < 64 ? bhh[g] : 0.0f);
        float a1 = 0.0f;
        const float* wr = Wih + g * EMB;
        #pragma unroll
        for (int k = 0; k < EMB; k += 2) {
            a0 = fmaf(wr[k],     e[k],     a0);
            a1 = fmaf(wr[k + 1], e[k + 1], a1);
        }
        int gate = g >> 5, j = g & 31;
        int hg = j >> 3, tg = (j >> 1) & 3, eb = j & 1;
        int pos = gate * 32 + tg * 8 + hg * 2 + eb;
        g_GI2[dir * (VOC * G3) + c * G3 + pos] = a0 + a1;
    } else {
        // pack B fragments (2*12*4*32 = 3072 uint2)
        for (int i = tid; i < 3072; i += 192) {
            int d    = i / 1536;
            int rem  = i % 1536;
            int nb   = rem / 128;
            int kc   = (rem / 32) & 3;
            int lane = rem & 31;
            int gid = lane >> 2, tg = lane & 3;
            const float* W = d ? Whh_b : Whh_f;
            int row = 8 * nb + gid;
            g_WF[i] = make_uint2(tf32_of(W[row * HID + 8 * kc + tg]),
                                 tf32_of(W[row * HID + 8 * kc + tg + 4]));
        }
    }
}

// exact dual-slot GRU activation: 8 MUFU per 2 hidden units
__device__ __forceinline__ void act_pair(float xr0, float xz0, float xr1, float xz1,
                                         float ghn0, float gin0,
                                         float ghn1, float gin1,
                                         float& h0, float& h1,
                                         float& m0, float& m1) {
    const float NL  = -1.4426950408889634f;
    const float NL2 = -2.8853900817779268f;
    float a1 = 1.0f + ex2f(fmaxf(xr0, -15.0f) * NL);
    float a2 = 1.0f + ex2f(fmaxf(xz0, -15.0f) * NL);
    float a3 = 1.0f + ex2f(fmaxf(xr1, -15.0f) * NL);
    float a4 = 1.0f + ex2f(fmaxf(xz1, -15.0f) * NL);
    float q12 = a1 * a2, q34 = a3 * a4;
    float ip = rcpf(q12 * q34);
    float t = q34 * ip, u = q12 * ip;
    float r0 = a2 * t, z0 = a1 * t;
    float r1 = a4 * u, z1 = a3 * u;
    float xn0 = fmaf(r0, ghn0, gin0);
    float xn1 = fmaf(r1, ghn1, gin1);
    float c0 = 1.0f + ex2f(fmaxf(xn0, -7.5f) * NL2);
    float c1 = 1.0f + ex2f(fmaxf(xn1, -7.5f) * NL2);
    float ic = rcpf(c0 * c1);
    float n0 = fmaf(2.0f * c1, ic, -1.0f);     // tanh(xn0)
    float n1 = fmaf(2.0f * c0, ic, -1.0f);
    h0 = fmaf(z0, h0 - n0, n0);
    h1 = fmaf(z1, h1 - n1, n1);
    m0 = fmaxf(m0, h0);
    m1 = fmaxf(m1, h1);
}

// ---------------------------------------------------------------------------
// Kernel 2: tensor-core GRU. One warp = 16 sequences, one direction.
// 48 tf32 MMAs/step (single-term A), shfl D->A exchange, LDG.128 gi loads.
// ---------------------------------------------------------------------------
__global__ __launch_bounds__(64)
void gru_mma(const int* __restrict__ x,
             const float* __restrict__ bhh_f,
             const float* __restrict__ bhh_b,
             float* __restrict__ out) {
    int w    = blockIdx.x * 2 + (threadIdx.x >> 5);   // 0..2047
    int lane = threadIdx.x & 31;
    int gid  = lane >> 2;
    int tig  = lane & 3;
    int dir  = w >> 10;
    int seq0 = (w & 1023) << 4;

    const float* __restrict__ GI  = g_GI2 + dir * (VOC * G3);
    const uint2* __restrict__ WF  = g_WF + dir * (12 * 4 * 32);
    const float* __restrict__ bhh = dir ? bhh_b : bhh_f;

    // B fragments (coalesced preload)
    unsigned bf[12][4][2];
    #pragma unroll
    for (int nb = 0; nb < 12; nb++)
        #pragma unroll
        for (int kc = 0; kc < 4; kc++) {
            uint2 v = WF[(nb * 4 + kc) * 32 + lane];
            bf[nb][kc][0] = v.x;
            bf[nb][kc][1] = v.y;
        }
    float bn0 = bhh[64 + 8 * 0 + 2 * tig], bn0b = bhh[64 + 8 * 0 + 2 * tig + 1];
    float bn1 = bhh[64 + 8 * 1 + 2 * tig], bn1b = bhh[64 + 8 * 1 + 2 * tig + 1];
    float bn2 = bhh[64 + 8 * 2 + 2 * tig], bn2b = bhh[64 + 8 * 2 + 2 * tig + 1];
    float bn3 = bhh[64 + 8 * 3 + 2 * tig], bn3b = bhh[64 + 8 * 3 + 2 * tig + 1];

    const int* xA = x + (seq0 + gid) * TCH;
    const int* xB = x + (seq0 + gid + 8) * TCH;

    int srcA = (lane & 28) | (tig >> 1);    // owner quad-lane for cols 8kc+tig
    int srcB = srcA + 2;                    // owner for cols 8kc+tig+4
    int esel = lane & 1;

    float hn[4][4], hmax[4][4];
    #pragma unroll
    for (int hg = 0; hg < 4; hg++)
        #pragma unroll
        for (int s = 0; s < 4; s++) { hn[hg][s] = 0.0f; hmax[hg][s] = -CUDART_INF_F; }

    int t0 = dir ? (TCH - 1) : 0;
    int cA = xA[t0], cB = xB[t0];

    #pragma unroll 1
    for (int tt = 0; tt < TCH; ++tt) {
        // prefetch next step's characters
        int tn  = dir ? ((TCH - 2 - tt) & (TCH - 1)) : ((tt + 1) & (TCH - 1));
        int cAn = xA[tn], cBn = xB[tn];

        const float4* gA4 = (const float4*)(GI + cA * G3);
        const float4* gB4 = (const float4*)(GI + cB * G3);
        float4 ra0 = gA4[tig * 2],      ra1 = gA4[tig * 2 + 1];
        float4 za0 = gA4[8 + tig * 2],  za1 = gA4[8 + tig * 2 + 1];
        float4 na0 = gA4[16 + tig * 2], na1 = gA4[16 + tig * 2 + 1];
        float4 rb0 = gB4[tig * 2],      rb1 = gB4[tig * 2 + 1];
        float4 zb0 = gB4[8 + tig * 2],  zb1 = gB4[8 + tig * 2 + 1];
        float4 nb0 = gB4[16 + tig * 2], nb1 = gB4[16 + tig * 2 + 1];

        // D-layout h -> A fragments (tf32, quad-local shfl exchange)
        unsigned a[4][4];
        {
            unsigned hq[4][4];
            #pragma unroll
            for (int hg = 0; hg < 4; hg++)
                #pragma unroll
                for (int s = 0; s < 4; s++) hq[hg][s] = tf32_of(hn[hg][s]);
            #pragma unroll
            for (int kc = 0; kc < 4; kc++) {
                unsigned p0 = __shfl_sync(0xffffffffu, hq[kc][0], srcA);
                unsigned p1 = __shfl_sync(0xffffffffu, hq[kc][1], srcA);
                unsigned p2 = __shfl_sync(0xffffffffu, hq[kc][2], srcA);
                unsigned p3 = __shfl_sync(0xffffffffu, hq[kc][3], srcA);
                unsigned q0 = __shfl_sync(0xffffffffu, hq[kc][0], srcB);
                unsigned q1 = __shfl_sync(0xffffffffu, hq[kc][1], srcB);
                unsigned q2 = __shfl_sync(0xffffffffu, hq[kc][2], srcB);
                unsigned q3 = __shfl_sync(0xffffffffu, hq[kc][3], srcB);
                a[kc][0] = esel ? p1 : p0;
                a[kc][1] = esel ? p3 : p2;
                a[kc][2] = esel ? q1 : q0;
                a[kc][3] = esel ? q3 : q2;
            }
        }

        // accumulators: acc[nb][slot]; nb = gate*4 + hg
        float acc[12][4];
        acc[0][0]=ra0.x;  acc[0][1]=ra0.y;  acc[1][0]=ra0.z;  acc[1][1]=ra0.w;
        acc[2][0]=ra1.x;  acc[2][1]=ra1.y;  acc[3][0]=ra1.z;  acc[3][1]=ra1.w;
        acc[0][2]=rb0.x;  acc[0][3]=rb0.y;  acc[1][2]=rb0.z;  acc[1][3]=rb0.w;
        acc[2][2]=rb1.x;  acc[2][3]=rb1.y;  acc[3][2]=rb1.z;  acc[3][3]=rb1.w;
        acc[4][0]=za0.x;  acc[4][1]=za0.y;  acc[5][0]=za0.z;  acc[5][1]=za0.w;
        acc[6][0]=za1.x;  acc[6][1]=za1.y;  acc[7][0]=za1.z;  acc[7][1]=za1.w;
        acc[4][2]=zb0.x;  acc[4][3]=zb0.y;  acc[5][2]=zb0.z;  acc[5][3]=zb0.w;
        acc[6][2]=zb1.x;  acc[6][3]=zb1.y;  acc[7][2]=zb1.z;  acc[7][3]=zb1.w;
        acc[8][0]=bn0;  acc[8][1]=bn0b;  acc[9][0]=bn1;  acc[9][1]=bn1b;
        acc[10][0]=bn2; acc[10][1]=bn2b; acc[11][0]=bn3; acc[11][1]=bn3b;
        acc[8][2]=bn0;  acc[8][3]=bn0b;  acc[9][2]=bn1;  acc[9][3]=bn1b;
        acc[10][2]=bn2; acc[10][3]=bn2b; acc[11][2]=bn3; acc[11][3]=bn3b;

        float gin[4][4];
        gin[0][0]=na0.x; gin[0][1]=na0.y; gin[1][0]=na0.z; gin[1][1]=na0.w;
        gin[2][0]=na1.x; gin[2][1]=na1.y; gin[3][0]=na1.z; gin[3][1]=na1.w;
        gin[0][2]=nb0.x; gin[0][3]=nb0.y; gin[1][2]=nb0.z; gin[1][3]=nb0.w;
        gin[2][2]=nb1.x; gin[2][3]=nb1.y; gin[3][2]=nb1.z; gin[3][3]=nb1.w;

        #pragma unroll
        for (int kc = 0; kc < 4; kc++)
            #pragma unroll
            for (int nb = 0; nb < 12; nb++)
                mma_tf32(acc[nb], a[kc], bf[nb][kc]);

        #pragma unroll
        for (int hg = 0; hg < 4; hg++) {
            act_pair(acc[hg][0], acc[4 + hg][0], acc[hg][1], acc[4 + hg][1],
                     acc[8 + hg][0], gin[hg][0], acc[8 + hg][1], gin[hg][1],
                     hn[hg][0], hn[hg][1], hmax[hg][0], hmax[hg][1]);
            act_pair(acc[hg][2], acc[4 + hg][2], acc[hg][3], acc[4 + hg][3],
                     acc[8 + hg][2], gin[hg][2], acc[8 + hg][3], gin[hg][3],
                     hn[hg][2], hn[hg][3], hmax[hg][2], hmax[hg][3]);
        }

        cA = cAn; cB = cBn;
    }

    int sA = seq0 + gid, sB = seq0 + gid + 8;
    #pragma unroll
    for (int hg = 0; hg < 4; hg++) {
        int col = 8 * hg + 2 * tig;
        *(float2*)(out + sA * 64 + dir * 32 + col) = make_float2(hmax[hg][0], hmax[hg][1]);
        *(float2*)(out + sB * 64 + dir * 32 + col) = make_float2(hmax[hg][2], hmax[hg][3]);
    }
}

// ---------------------------------------------------------------------------
// kernel_launch
// ---------------------------------------------------------------------------
extern "C" void kernel_launch(void* const* d_in, const int* in_sizes, int n_in,
                              void* d_out, int out_size) {
    const int*   x     = (const int*)  d_in[0];
    const float* emb   = (const float*)d_in[1];
    const float* Wih_f = (const float*)d_in[2];
    const float* Whh_f = (const float*)d_in[3];
    const float* bih_f = (const float*)d_in[4];
    const float* bhh_f = (const float*)d_in[5];
    const float* Wih_b = (const float*)d_in[6];
    const float* Whh_b = (const float*)d_in[7];
    const float* bih_b = (const float*)d_in[8];
    const float* bhh_b = (const float*)d_in[9];
    float* out = (float*)d_out;

    build_tables<<<VOC + 1, 192>>>(emb, Wih_f, bih_f, bhh_f,
                                   Wih_b, bih_b, bhh_b, Whh_f, Whh_b);

    // 2048 warps in 64-thread blocks
    gru_mma<<<NGRP / 2, 64>>>(x, bhh_f, bhh_b, out);
}

// round 6
// speedup vs baseline: 2.1031x; 1.0120x over previous
#include <cuda_runtime.h>
#include <cuda_bf16.h>
#include <math_constants.h>

#define BATCH 64
#define SEQ   256
#define TCH   16
#define VOC   262
#define EMB   64
#define HID   32
#define G3    96
#define NSEQ  (BATCH*SEQ)
#define NGRP  2048            // (16-seq, dir) warps

// Tables (device globals — no allocation allowed)
// Permuted GI rows: pos(gate,j) = gate*32 + tig*8 + hg*2 + e  (j = 8hg+2tig+e)
__device__ __align__(128) float g_GI2[2 * VOC * G3];
// Pre-packed tf32 B fragments: [dir][nb][kc][lane] = (W[8nb+gid][8kc+tig], [+4])
__device__ uint2 g_WF[2 * 12 * 4 * 32];

__device__ __forceinline__ unsigned tf32_of(float f) {
    unsigned r;
    asm("cvt.rna.tf32.f32 %0, %1;" : "=r"(r) : "f"(f));
    return r;
}
__device__ __forceinline__ float ex2f(float a) {
    float r;
    asm("ex2.approx.f32 %0, %1;" : "=f"(r) : "f"(a));
    return r;
}
__device__ __forceinline__ float rcpf(float a) {
    float r;
    asm("rcp.approx.f32 %0, %1;" : "=f"(r) : "f"(a));
    return r;
}
__device__ __forceinline__ void mma_tf32(float* d, const unsigned* a,
                                         unsigned b0, unsigned b1) {
    asm("mma.sync.aligned.m16n8k8.row.col.f32.tf32.tf32.f32 "
        "{%0,%1,%2,%3}, {%4,%5,%6,%7}, {%8,%9}, {%0,%1,%2,%3};"
        : "+f"(d[0]), "+f"(d[1]), "+f"(d[2]), "+f"(d[3])
        : "r"(a[0]), "r"(a[1]), "r"(a[2]), "r"(a[3]),
          "r"(b0), "r"(b1));
}

// ---------------------------------------------------------------------------
// Kernel 1: GI tables (permuted layout, bhh folded for r,z) + B-fragment pack
// grid = VOC+1, block = 192 (tid<96: dir 0, tid>=96: dir 1)
// ---------------------------------------------------------------------------
__global__ void build_tables(const float* __restrict__ emb,
                             const float* __restrict__ Wih_f,
                             const float* __restrict__ bih_f,
                             const float* __restrict__ bhh_f,
                             const float* __restrict__ Wih_b,
                             const float* __restrict__ bih_b,
                             const float* __restrict__ bhh_b,
                             const float* __restrict__ Whh_f,
                             const float* __restrict__ Whh_b) {
    int c   = blockIdx.x;
    int tid = threadIdx.x;
    if (c < VOC) {
        int dir = tid / 96;
        int g   = tid % 96;
        __shared__ float e[EMB];
        if (tid < EMB) e[tid] = emb[c * EMB + tid];
        __syncthreads();
        const float* Wih = dir ? Wih_b : Wih_f;
        const float* bih = dir ? bih_b : bih_f;
        const float* bhh = dir ? bhh_b : bhh_f;
        float a0 = bih[g] + (g < 64 ? bhh[g] : 0.0f);
        float a1 = 0.0f;
        const float* wr = Wih + g * EMB;
        #pragma unroll
        for (int k = 0; k < EMB; k += 2) {
            a0 = fmaf(wr[k],     e[k],     a0);
            a1 = fmaf(wr[k + 1], e[k + 1], a1);
        }
        int gate = g >> 5, j = g & 31;
        int hg = j >> 3, tg = (j >> 1) & 3, eb = j & 1;
        int pos = gate * 32 + tg * 8 + hg * 2 + eb;
        g_GI2[dir * (VOC * G3) + c * G3 + pos] = a0 + a1;
    } else {
        // pack B fragments (2*12*4*32 = 3072 uint2)
        for (int i = tid; i < 3072; i += 192) {
            int d    = i / 1536;
            int rem  = i % 1536;
            int nb   = rem / 128;
            int kc   = (rem / 32) & 3;
            int lane = rem & 31;
            int gid = lane >> 2, tg = lane & 3;
            const float* W = d ? Whh_b : Whh_f;
            int row = 8 * nb + gid;
            g_WF[i] = make_uint2(tf32_of(W[row * HID + 8 * kc + tg]),
                                 tf32_of(W[row * HID + 8 * kc + tg + 4]));
        }
    }
}

// exact dual-slot GRU activation: shared-rcp, no clamps (args bounded ~|12|)
__device__ __forceinline__ void act_pair(float xr0, float xz0, float xr1, float xz1,
                                         float ghn0, float gin0,
                                         float ghn1, float gin1,
                                         float& h0, float& h1,
                                         float& m0, float& m1) {
    const float NL  = -1.4426950408889634f;
    const float NL2 = -2.8853900817779268f;
    float a1 = 1.0f + ex2f(xr0 * NL);
    float a2 = 1.0f + ex2f(xz0 * NL);
    float a3 = 1.0f + ex2f(xr1 * NL);
    float a4 = 1.0f + ex2f(xz1 * NL);
    float q12 = a1 * a2, q34 = a3 * a4;
    float ip = rcpf(q12 * q34);
    float t = q34 * ip, u = q12 * ip;
    float r0 = a2 * t, z0 = a1 * t;
    float r1 = a4 * u, z1 = a3 * u;
    float xn0 = fmaf(r0, ghn0, gin0);
    float xn1 = fmaf(r1, ghn1, gin1);
    float c0 = 1.0f + ex2f(xn0 * NL2);
    float c1 = 1.0f + ex2f(xn1 * NL2);
    float ic = rcpf(c0 * c1);
    float n0 = fmaf(2.0f * c1, ic, -1.0f);     // tanh(xn0)
    float n1 = fmaf(2.0f * c0, ic, -1.0f);
    h0 = fmaf(z0, h0 - n0, n0);
    h1 = fmaf(z1, h1 - n1, n1);
    m0 = fmaxf(m0, h0);
    m1 = fmaxf(m1, h1);
}

// ---------------------------------------------------------------------------
// Kernel 2: tensor-core GRU. One warp = 16 sequences, one direction.
// 48 tf32 MMAs/step (single-term A), B fragments in shared memory (one
// block-wide copy), shfl D->A exchange, LDG.128 gi loads.
// Blocks are direction-uniform: dir = blockIdx.x >> 9.
// ---------------------------------------------------------------------------
__global__ __launch_bounds__(64, 6)
void gru_mma(const int* __restrict__ x,
             const float* __restrict__ bhh_f,
             const float* __restrict__ bhh_b,
             float* __restrict__ out) {
    __shared__ uint2 s_bf[12 * 4 * 32];     // 12 KB, shared by both warps

    int tid  = threadIdx.x;
    int w    = blockIdx.x * 2 + (tid >> 5);   // 0..2047
    int lane = tid & 31;
    int gid  = lane >> 2;
    int tig  = lane & 3;
    int dir  = blockIdx.x >> 9;               // block-uniform
    int seq0 = (w & 1023) << 4;

    // copy this direction's B fragments to smem (coalesced, once per block)
    {
        const uint2* src = g_WF + dir * 1536;
        #pragma unroll
        for (int i = 0; i < 24; i++)
            s_bf[tid + 64 * i] = src[tid + 64 * i];
    }
    __syncthreads();

    const float* __restrict__ GI  = g_GI2 + dir * (VOC * G3);
    const float* __restrict__ bhh = dir ? bhh_b : bhh_f;

    float bn0 = bhh[64 + 2 * tig],      bn0b = bhh[64 + 2 * tig + 1];
    float bn1 = bhh[64 + 8 + 2 * tig],  bn1b = bhh[64 + 8 + 2 * tig + 1];
    float bn2 = bhh[64 + 16 + 2 * tig], bn2b = bhh[64 + 16 + 2 * tig + 1];
    float bn3 = bhh[64 + 24 + 2 * tig], bn3b = bhh[64 + 24 + 2 * tig + 1];

    const int* xA = x + (seq0 + gid) * TCH;
    const int* xB = x + (seq0 + gid + 8) * TCH;

    int srcA = (lane & 28) | (tig >> 1);    // owner quad-lane for cols 8kc+tig
    int srcB = srcA + 2;                    // owner for cols 8kc+tig+4
    int esel = lane & 1;

    float hn[4][4], hmax[4][4];
    #pragma unroll
    for (int hg = 0; hg < 4; hg++)
        #pragma unroll
        for (int s = 0; s < 4; s++) { hn[hg][s] = 0.0f; hmax[hg][s] = -CUDART_INF_F; }

    int t0 = dir ? (TCH - 1) : 0;
    int cA = xA[t0], cB = xB[t0];

    #pragma unroll 1
    for (int tt = 0; tt < TCH; ++tt) {
        // prefetch next step's characters
        int tn  = dir ? ((TCH - 2 - tt) & (TCH - 1)) : ((tt + 1) & (TCH - 1));
        int cAn = xA[tn], cBn = xB[tn];

        const float4* gA4 = (const float4*)(GI + cA * G3);
        const float4* gB4 = (const float4*)(GI + cB * G3);
        float4 ra0 = gA4[tig * 2],      ra1 = gA4[tig * 2 + 1];
        float4 za0 = gA4[8 + tig * 2],  za1 = gA4[8 + tig * 2 + 1];
        float4 na0 = gA4[16 + tig * 2], na1 = gA4[16 + tig * 2 + 1];
        float4 rb0 = gB4[tig * 2],      rb1 = gB4[tig * 2 + 1];
        float4 zb0 = gB4[8 + tig * 2],  zb1 = gB4[8 + tig * 2 + 1];
        float4 nb0 = gB4[16 + tig * 2], nb1 = gB4[16 + tig * 2 + 1];

        // D-layout h -> A fragments (tf32, quad-local shfl exchange)
        unsigned a[4][4];
        #pragma unroll
        for (int kc = 0; kc < 4; kc++) {
            unsigned h0 = tf32_of(hn[kc][0]);
            unsigned h1 = tf32_of(hn[kc][1]);
            unsigned h2 = tf32_of(hn[kc][2]);
            unsigned h3 = tf32_of(hn[kc][3]);
            unsigned p0 = __shfl_sync(0xffffffffu, h0, srcA);
            unsigned p1 = __shfl_sync(0xffffffffu, h1, srcA);
            unsigned p2 = __shfl_sync(0xffffffffu, h2, srcA);
            unsigned p3 = __shfl_sync(0xffffffffu, h3, srcA);
            unsigned q0 = __shfl_sync(0xffffffffu, h0, srcB);
            unsigned q1 = __shfl_sync(0xffffffffu, h1, srcB);
            unsigned q2 = __shfl_sync(0xffffffffu, h2, srcB);
            unsigned q3 = __shfl_sync(0xffffffffu, h3, srcB);
            a[kc][0] = esel ? p1 : p0;
            a[kc][1] = esel ? p3 : p2;
            a[kc][2] = esel ? q1 : q0;
            a[kc][3] = esel ? q3 : q2;
        }

        // accumulators: acc[nb][slot]; nb = gate*4 + hg
        float acc[12][4];
        acc[0][0]=ra0.x;  acc[0][1]=ra0.y;  acc[1][0]=ra0.z;  acc[1][1]=ra0.w;
        acc[2][0]=ra1.x;  acc[2][1]=ra1.y;  acc[3][0]=ra1.z;  acc[3][1]=ra1.w;
        acc[0][2]=rb0.x;  acc[0][3]=rb0.y;  acc[1][2]=rb0.z;  acc[1][3]=rb0.w;
        acc[2][2]=rb1.x;  acc[2][3]=rb1.y;  acc[3][2]=rb1.z;  acc[3][3]=rb1.w;
        acc[4][0]=za0.x;  acc[4][1]=za0.y;  acc[5][0]=za0.z;  acc[5][1]=za0.w;
        acc[6][0]=za1.x;  acc[6][1]=za1.y;  acc[7][0]=za1.z;  acc[7][1]=za1.w;
        acc[4][2]=zb0.x;  acc[4][3]=zb0.y;  acc[5][2]=zb0.z;  acc[5][3]=zb0.w;
        acc[6][2]=zb1.x;  acc[6][3]=zb1.y;  acc[7][2]=zb1.z;  acc[7][3]=zb1.w;
        acc[8][0]=bn0;  acc[8][1]=bn0b;  acc[9][0]=bn1;  acc[9][1]=bn1b;
        acc[10][0]=bn2; acc[10][1]=bn2b; acc[11][0]=bn3; acc[11][1]=bn3b;
        acc[8][2]=bn0;  acc[8][3]=bn0b;  acc[9][2]=bn1;  acc[9][3]=bn1b;
        acc[10][2]=bn2; acc[10][3]=bn2b; acc[11][2]=bn3; acc[11][3]=bn3b;

        float gin[4][4];
        gin[0][0]=na0.x; gin[0][1]=na0.y; gin[1][0]=na0.z; gin[1][1]=na0.w;
        gin[2][0]=na1.x; gin[2][1]=na1.y; gin[3][0]=na1.z; gin[3][1]=na1.w;
        gin[0][2]=nb0.x; gin[0][3]=nb0.y; gin[1][2]=nb0.z; gin[1][3]=nb0.w;
        gin[2][2]=nb1.x; gin[2][3]=nb1.y; gin[3][2]=nb1.z; gin[3][3]=nb1.w;

        #pragma unroll
        for (int kc = 0; kc < 4; kc++)
            #pragma unroll
            for (int nb = 0; nb < 12; nb++) {
                uint2 b = s_bf[(nb * 4 + kc) * 32 + lane];
                mma_tf32(acc[nb], a[kc], b.x, b.y);
            }

        #pragma unroll
        for (int hg = 0; hg < 4; hg++) {
            act_pair(acc[hg][0], acc[4 + hg][0], acc[hg][1], acc[4 + hg][1],
                     acc[8 + hg][0], gin[hg][0], acc[8 + hg][1], gin[hg][1],
                     hn[hg][0], hn[hg][1], hmax[hg][0], hmax[hg][1]);
            act_pair(acc[hg][2], acc[4 + hg][2], acc[hg][3], acc[4 + hg][3],
                     acc[8 + hg][2], gin[hg][2], acc[8 + hg][3], gin[hg][3],
                     hn[hg][2], hn[hg][3], hmax[hg][2], hmax[hg][3]);
        }

        cA = cAn; cB = cBn;
    }

    int sA = seq0 + gid, sB = seq0 + gid + 8;
    #pragma unroll
    for (int hg = 0; hg < 4; hg++) {
        int col = 8 * hg + 2 * tig;
        *(float2*)(out + sA * 64 + dir * 32 + col) = make_float2(hmax[hg][0], hmax[hg][1]);
        *(float2*)(out + sB * 64 + dir * 32 + col) = make_float2(hmax[hg][2], hmax[hg][3]);
    }
}

// ---------------------------------------------------------------------------
// kernel_launch
// ---------------------------------------------------------------------------
extern "C" void kernel_launch(void* const* d_in, const int* in_sizes, int n_in,
                              void* d_out, int out_size) {
    const int*   x     = (const int*)  d_in[0];
    const float* emb   = (const float*)d_in[1];
    const float* Wih_f = (const float*)d_in[2];
    const float* Whh_f = (const float*)d_in[3];
    const float* bih_f = (const float*)d_in[4];
    const float* bhh_f = (const float*)d_in[5];
    const float* Wih_b = (const float*)d_in[6];
    const float* Whh_b = (const float*)d_in[7];
    const float* bih_b = (const float*)d_in[8];
    const float* bhh_b = (const float*)d_in[9];
    float* out = (float*)d_out;

    build_tables<<<VOC + 1, 192>>>(emb, Wih_f, bih_f, bhh_f,
                                   Wih_b, bih_b, bhh_b, Whh_f, Whh_b);

    // 2048 warps in 64-thread blocks; blocks 0..511 dir0, 512..1023 dir1
    gru_mma<<<NGRP / 2, 64>>>(x, bhh_f, bhh_b, out);
}

// round 7
// speedup vs baseline: 2.6007x; 1.2366x over previous
#include <cuda_runtime.h>
#include <cuda_bf16.h>
#include <math_constants.h>

#define BATCH 64
#define SEQ   256
#define TCH   16
#define VOC   262
#define EMB   64
#define HID   32
#define G3    96
#define NSEQ  (BATCH*SEQ)
#define NGRP  2048            // (16-seq, dir) warps

// Tables (device globals — no allocation allowed)
// Permuted GI rows: pos(gate,j) = gate*32 + tig*8 + hg*2 + e
// r,z entries pre-scaled by 0.5 (for sigmoid-via-tanh); bhh folded for r,z.
__device__ __align__(128) float g_GI2[2 * VOC * G3];
// Pre-packed tf32 B fragments: [dir][nb][kc][lane]; nb<8 rows pre-scaled 0.5
__device__ uint2 g_WF[2 * 12 * 4 * 32];

__device__ __forceinline__ unsigned tf32_of(float f) {
    unsigned r;
    asm("cvt.rna.tf32.f32 %0, %1;" : "=r"(r) : "f"(f));
    return r;
}
__device__ __forceinline__ float tanhapx(float x) {
    float r;
    asm("tanh.approx.f32 %0, %1;" : "=f"(r) : "f"(x));
    return r;
}
__device__ __forceinline__ void mma_tf32(float* d, const unsigned* a,
                                         unsigned b0, unsigned b1) {
    asm("mma.sync.aligned.m16n8k8.row.col.f32.tf32.tf32.f32 "
        "{%0,%1,%2,%3}, {%4,%5,%6,%7}, {%8,%9}, {%0,%1,%2,%3};"
        : "+f"(d[0]), "+f"(d[1]), "+f"(d[2]), "+f"(d[3])
        : "r"(a[0]), "r"(a[1]), "r"(a[2]), "r"(a[3]),
          "r"(b0), "r"(b1));
}

// ---------------------------------------------------------------------------
// Kernel 1: GI tables (permuted, r/z pre-scaled 0.5, bhh folded for r,z)
// + B-fragment pack (r,z rows scaled 0.5). grid = VOC+1, block = 192.
// ---------------------------------------------------------------------------
__global__ void build_tables(const float* __restrict__ emb,
                             const float* __restrict__ Wih_f,
                             const float* __restrict__ bih_f,
                             const float* __restrict__ bhh_f,
                             const float* __restrict__ Wih_b,
                             const float* __restrict__ bih_b,
                             const float* __restrict__ bhh_b,
                             const float* __restrict__ Whh_f,
                             const float* __restrict__ Whh_b) {
    int c   = blockIdx.x;
    int tid = threadIdx.x;
    if (c < VOC) {
        int dir = tid / 96;
        int g   = tid % 96;
        __shared__ float e[EMB];
        if (tid < EMB) e[tid] = emb[c * EMB + tid];
        __syncthreads();
        const float* Wih = dir ? Wih_b : Wih_f;
        const float* bih = dir ? bih_b : bih_f;
        const float* bhh = dir ? bhh_b : bhh_f;
        float a0 = bih[g] + (g < 64 ? bhh[g] : 0.0f);
        float a1 = 0.0f;
        const float* wr = Wih + g * EMB;
        #pragma unroll
        for (int k = 0; k < EMB; k += 2) {
            a0 = fmaf(wr[k],     e[k],     a0);
            a1 = fmaf(wr[k + 1], e[k + 1], a1);
        }
        float v = a0 + a1;
        if (g < 64) v *= 0.5f;               // sigmoid-via-tanh prescale
        int gate = g >> 5, j = g & 31;
        int hg = j >> 3, tg = (j >> 1) & 3, eb = j & 1;
        int pos = gate * 32 + tg * 8 + hg * 2 + eb;
        g_GI2[dir * (VOC * G3) + c * G3 + pos] = v;
    } else {
        // pack B fragments (2*12*4*32 = 3072 uint2)
        for (int i = tid; i < 3072; i += 192) {
            int d    = i / 1536;
            int rem  = i % 1536;
            int nb   = rem / 128;
            int kc   = (rem / 32) & 3;
            int lane = rem & 31;
            int gid = lane >> 2, tg = lane & 3;
            const float* W = d ? Whh_b : Whh_f;
            int row = 8 * nb + gid;
            float s = (nb < 8) ? 0.5f : 1.0f;    // r,z rows prescaled
            g_WF[i] = make_uint2(tf32_of(s * W[row * HID + 8 * kc + tg]),
                                 tf32_of(s * W[row * HID + 8 * kc + tg + 4]));
        }
    }
}

// ---------------------------------------------------------------------------
// Kernel 2: tensor-core GRU. One warp = 16 sequences, one direction.
// 48 tf32 MMAs/step, B in smem, smem double-buffered D->A exchange,
// MUFU.TANH activations. Blocks dir-uniform: dir = blockIdx.x >> 9.
// ---------------------------------------------------------------------------
__global__ __launch_bounds__(64, 7)
void gru_mma(const int* __restrict__ x,
             const float* __restrict__ bhh_f,
             const float* __restrict__ bhh_b,
             float* __restrict__ out) {
    __shared__ uint2    s_bf[12 * 4 * 32];   // 12 KB B fragments
    __shared__ unsigned shx[2][2][16][36];   // exchange: [warp][buf][row][col]

    int tid  = threadIdx.x;
    int w    = blockIdx.x * 2 + (tid >> 5);   // 0..2047
    int lane = tid & 31;
    int wb   = tid >> 5;
    int gid  = lane >> 2;
    int tig  = lane & 3;
    int dir  = blockIdx.x >> 9;               // block-uniform
    int seq0 = (w & 1023) << 4;

    // copy this direction's B fragments to smem (coalesced, once per block)
    {
        const uint2* src = g_WF + dir * 1536;
        #pragma unroll
        for (int i = 0; i < 24; i++)
            s_bf[tid + 64 * i] = src[tid + 64 * i];
    }
    __syncthreads();

    const float* __restrict__ GI  = g_GI2 + dir * (VOC * G3);
    const float* __restrict__ bhh = dir ? bhh_b : bhh_f;

    float bn0 = bhh[64 + 2 * tig],      bn0b = bhh[64 + 2 * tig + 1];
    float bn1 = bhh[64 + 8 + 2 * tig],  bn1b = bhh[64 + 8 + 2 * tig + 1];
    float bn2 = bhh[64 + 16 + 2 * tig], bn2b = bhh[64 + 16 + 2 * tig + 1];
    float bn3 = bhh[64 + 24 + 2 * tig], bn3b = bhh[64 + 24 + 2 * tig + 1];

    const int* xA = x + (seq0 + gid) * TCH;
    const int* xB = x + (seq0 + gid + 8) * TCH;

    float hn[4][4], hmax[4][4];
    #pragma unroll
    for (int hg = 0; hg < 4; hg++)
        #pragma unroll
        for (int s = 0; s < 4; s++) { hn[hg][s] = 0.0f; hmax[hg][s] = -CUDART_INF_F; }

    int t0 = dir ? (TCH - 1) : 0;
    int cA = xA[t0], cB = xB[t0];

    #pragma unroll 1
    for (int tt = 0; tt < TCH; ++tt) {
        // prefetch next step's characters
        int tn  = dir ? ((TCH - 2 - tt) & (TCH - 1)) : ((tt + 1) & (TCH - 1));
        int cAn = xA[tn], cBn = xB[tn];

        const float4* gA4 = (const float4*)(GI + cA * G3);
        const float4* gB4 = (const float4*)(GI + cB * G3);
        float4 ra0 = gA4[tig * 2],      ra1 = gA4[tig * 2 + 1];
        float4 za0 = gA4[8 + tig * 2],  za1 = gA4[8 + tig * 2 + 1];
        float4 na0 = gA4[16 + tig * 2], na1 = gA4[16 + tig * 2 + 1];
        float4 rb0 = gB4[tig * 2],      rb1 = gB4[tig * 2 + 1];
        float4 zb0 = gB4[8 + tig * 2],  zb1 = gB4[8 + tig * 2 + 1];
        float4 nb0 = gB4[16 + tig * 2], nb1 = gB4[16 + tig * 2 + 1];

        // D-layout h -> smem (tf32), double-buffered
        int buf = tt & 1;
        unsigned (*sb)[36] = shx[wb][buf];
        #pragma unroll
        for (int hg = 0; hg < 4; hg++) {
            *(uint2*)&sb[gid][8 * hg + 2 * tig] =
                make_uint2(tf32_of(hn[hg][0]), tf32_of(hn[hg][1]));
            *(uint2*)&sb[gid + 8][8 * hg + 2 * tig] =
                make_uint2(tf32_of(hn[hg][2]), tf32_of(hn[hg][3]));
        }
        __syncwarp();

        // A fragments from smem (conflict-free LDS.32)
        unsigned a[4][4];
        #pragma unroll
        for (int kc = 0; kc < 4; kc++) {
            a[kc][0] = sb[gid][8 * kc + tig];
            a[kc][1] = sb[gid + 8][8 * kc + tig];
            a[kc][2] = sb[gid][8 * kc + tig + 4];
            a[kc][3] = sb[gid + 8][8 * kc + tig + 4];
        }

        // accumulators: acc[nb][slot]; nb = gate*4 + hg
        float acc[12][4];
        acc[0][0]=ra0.x;  acc[0][1]=ra0.y;  acc[1][0]=ra0.z;  acc[1][1]=ra0.w;
        acc[2][0]=ra1.x;  acc[2][1]=ra1.y;  acc[3][0]=ra1.z;  acc[3][1]=ra1.w;
        acc[0][2]=rb0.x;  acc[0][3]=rb0.y;  acc[1][2]=rb0.z;  acc[1][3]=rb0.w;
        acc[2][2]=rb1.x;  acc[2][3]=rb1.y;  acc[3][2]=rb1.z;  acc[3][3]=rb1.w;
        acc[4][0]=za0.x;  acc[4][1]=za0.y;  acc[5][0]=za0.z;  acc[5][1]=za0.w;
        acc[6][0]=za1.x;  acc[6][1]=za1.y;  acc[7][0]=za1.z;  acc[7][1]=za1.w;
        acc[4][2]=zb0.x;  acc[4][3]=zb0.y;  acc[5][2]=zb0.z;  acc[5][3]=zb0.w;
        acc[6][2]=zb1.x;  acc[6][3]=zb1.y;  acc[7][2]=zb1.z;  acc[7][3]=zb1.w;
        acc[8][0]=bn0;  acc[8][1]=bn0b;  acc[9][0]=bn1;  acc[9][1]=bn1b;
        acc[10][0]=bn2; acc[10][1]=bn2b; acc[11][0]=bn3; acc[11][1]=bn3b;
        acc[8][2]=bn0;  acc[8][3]=bn0b;  acc[9][2]=bn1;  acc[9][3]=bn1b;
        acc[10][2]=bn2; acc[10][3]=bn2b; acc[11][2]=bn3; acc[11][3]=bn3b;

        float gin[4][4];
        gin[0][0]=na0.x; gin[0][1]=na0.y; gin[1][0]=na0.z; gin[1][1]=na0.w;
        gin[2][0]=na1.x; gin[2][1]=na1.y; gin[3][0]=na1.z; gin[3][1]=na1.w;
        gin[0][2]=nb0.x; gin[0][3]=nb0.y; gin[1][2]=nb0.z; gin[1][3]=nb0.w;
        gin[2][2]=nb1.x; gin[2][3]=nb1.y; gin[3][2]=nb1.z; gin[3][3]=nb1.w;

        #pragma unroll
        for (int kc = 0; kc < 4; kc++)
            #pragma unroll
            for (int nb = 0; nb < 12; nb++) {
                uint2 b = s_bf[(nb * 4 + kc) * 32 + lane];
                mma_tf32(acc[nb], a[kc], b.x, b.y);
            }

        // activations: r,z via sigmoid(x)=0.5+0.5*tanh(x/2) (args prescaled)
        #pragma unroll
        for (int hg = 0; hg < 4; hg++)
            #pragma unroll
            for (int s = 0; s < 4; s++) {
                float r = fmaf(tanhapx(acc[hg][s]),     0.5f, 0.5f);
                float z = fmaf(tanhapx(acc[4 + hg][s]), 0.5f, 0.5f);
                float n = tanhapx(fmaf(r, acc[8 + hg][s], gin[hg][s]));
                float h = fmaf(z, hn[hg][s] - n, n);
                hn[hg][s] = h;
                hmax[hg][s] = fmaxf(hmax[hg][s], h);
            }

        cA = cAn; cB = cBn;
    }

    int sA = seq0 + gid, sB = seq0 + gid + 8;
    #pragma unroll
    for (int hg = 0; hg < 4; hg++) {
        int col = 8 * hg + 2 * tig;
        *(float2*)(out + sA * 64 + dir * 32 + col) = make_float2(hmax[hg][0], hmax[hg][1]);
        *(float2*)(out + sB * 64 + dir * 32 + col) = make_float2(hmax[hg][2], hmax[hg][3]);
    }
}

// ---------------------------------------------------------------------------
// kernel_launch
// ---------------------------------------------------------------------------
extern "C" void kernel_launch(void* const* d_in, const int* in_sizes, int n_in,
                              void* d_out, int out_size) {
    const int*   x     = (const int*)  d_in[0];
    const float* emb   = (const float*)d_in[1];
    const float* Wih_f = (const float*)d_in[2];
    const float* Whh_f = (const float*)d_in[3];
    const float* bih_f = (const float*)d_in[4];
    const float* bhh_f = (const float*)d_in[5];
    const float* Wih_b = (const float*)d_in[6];
    const float* Whh_b = (const float*)d_in[7];
    const float* bih_b = (const float*)d_in[8];
    const float* bhh_b = (const float*)d_in[9];
    float* out = (float*)d_out;

    build_tables<<<VOC + 1, 192>>>(emb, Wih_f, bih_f, bhh_f,
                                   Wih_b, bih_b, bhh_b, Whh_f, Whh_b);

    // 2048 warps in 64-thread blocks; blocks 0..511 dir0, 512..1023 dir1
    gru_mma<<<NGRP / 2, 64>>>(x, bhh_f, bhh_b, out);
}

// round 8
// speedup vs baseline: 3.9485x; 1.5182x over previous
#include <cuda_runtime.h>
#include <cuda_bf16.h>
#include <math_constants.h>

#define BATCH 64
#define SEQ   256
#define TCH   16
#define VOC   262
#define EMB   64
#define HID   32
#define G3    96
#define NSEQ  (BATCH*SEQ)

// Tables (device globals — no allocation allowed)
// Permuted GI rows: pos(gate,j) = gate*32 + tig*8 + hg*2 + e
// r,z entries pre-scaled by 0.5 (sigmoid-via-tanh); bhh folded for r,z.
__device__ __align__(128) float g_GI2[2 * VOC * G3];
// Pre-packed bf16 B fragments (m16n8k16): [dir][nb][kc][lane] = uint2(b0,b1)
// b0 = bf16x2(W[8nb+gid][16kc+2tig], [..+1]); b1 = same with k+8.
// nb<8 rows pre-scaled 0.5.
__device__ uint2 g_WF[2 * 12 * 2 * 32];

__device__ __forceinline__ unsigned packbf(float lo, float hi) {
    unsigned d;
    asm("cvt.rn.bf16x2.f32 %0, %1, %2;" : "=r"(d) : "f"(hi), "f"(lo));
    return d;
}
__device__ __forceinline__ float tanhapx(float x) {
    float r;
    asm("tanh.approx.f32 %0, %1;" : "=f"(r) : "f"(x));
    return r;
}
__device__ __forceinline__ void mma_bf16(float* d, const unsigned* a,
                                         unsigned b0, unsigned b1) {
    asm("mma.sync.aligned.m16n8k16.row.col.f32.bf16.bf16.f32 "
        "{%0,%1,%2,%3}, {%4,%5,%6,%7}, {%8,%9}, {%0,%1,%2,%3};"
        : "+f"(d[0]), "+f"(d[1]), "+f"(d[2]), "+f"(d[3])
        : "r"(a[0]), "r"(a[1]), "r"(a[2]), "r"(a[3]),
          "r"(b0), "r"(b1));
}

// ---------------------------------------------------------------------------
// Kernel 1: GI tables (permuted, r/z pre-scaled 0.5, bhh folded for r,z)
// + bf16 B-fragment pack. grid = VOC+1, block = 192. float4 Wih loads.
// ---------------------------------------------------------------------------
__global__ void build_tables(const float* __restrict__ emb,
                             const float* __restrict__ Wih_f,
                             const float* __restrict__ bih_f,
                             const float* __restrict__ bhh_f,
                             const float* __restrict__ Wih_b,
                             const float* __restrict__ bih_b,
                             const float* __restrict__ bhh_b,
                             const float* __restrict__ Whh_f,
                             const float* __restrict__ Whh_b) {
    int c   = blockIdx.x;
    int tid = threadIdx.x;
    if (c < VOC) {
        int dir = tid / 96;
        int g   = tid % 96;
        __shared__ float e[EMB];
        if (tid < EMB) e[tid] = emb[c * EMB + tid];
        __syncthreads();
        const float* Wih = dir ? Wih_b : Wih_f;
        const float* bih = dir ? bih_b : bih_f;
        const float* bhh = dir ? bhh_b : bhh_f;
        float a0 = bih[g] + (g < 64 ? bhh[g] : 0.0f);
        float a1 = 0.0f;
        const float4* wr4 = (const float4*)(Wih + g * EMB);
        #pragma unroll
        for (int k4 = 0; k4 < EMB / 4; k4++) {
            float4 wv = wr4[k4];
            a0 = fmaf(wv.x, e[4 * k4],     a0);
            a1 = fmaf(wv.y, e[4 * k4 + 1], a1);
            a0 = fmaf(wv.z, e[4 * k4 + 2], a0);
            a1 = fmaf(wv.w, e[4 * k4 + 3], a1);
        }
        float v = a0 + a1;
        if (g < 64) v *= 0.5f;               // sigmoid-via-tanh prescale
        int gate = g >> 5, j = g & 31;
        int hg = j >> 3, tg = (j >> 1) & 3, eb = j & 1;
        int pos = gate * 32 + tg * 8 + hg * 2 + eb;
        g_GI2[dir * (VOC * G3) + c * G3 + pos] = v;
    } else {
        // pack bf16 B fragments (2*12*2*32 = 1536 uint2)
        for (int i = tid; i < 1536; i += 192) {
            int d    = i / 768;
            int rem  = i % 768;
            int nb   = rem / 64;
            int kc   = (rem / 32) & 1;
            int lane = rem & 31;
            int gid = lane >> 2, tg = lane & 3;
            const float* W = d ? Whh_b : Whh_f;
            const float* row = W + (8 * nb + gid) * HID;
            float s = (nb < 8) ? 0.5f : 1.0f;    // r,z rows prescaled
            int k0 = 16 * kc + 2 * tg;
            g_WF[i] = make_uint2(packbf(s * row[k0],     s * row[k0 + 1]),
                                 packbf(s * row[k0 + 8], s * row[k0 + 9]));
        }
    }
}

// ---------------------------------------------------------------------------
// Kernel 2: bf16 tensor-core GRU. One warp = 16 sequences x 2 tasks, one dir.
// 24 bf16 m16n8k16 MMAs/step, B fragments in registers, LANE-LOCAL D->A
// conversion (no exchange at all), MUFU.TANH activations.
// Blocks dir-uniform: dir = blockIdx.x >> 8 (512 blocks).
// ---------------------------------------------------------------------------
__global__ __launch_bounds__(64, 5)
void gru_mma(const int* __restrict__ x,
             const float* __restrict__ bhh_f,
             const float* __restrict__ bhh_b,
             float* __restrict__ out) {
    int tid  = threadIdx.x;
    int wb   = tid >> 5;
    int lane = tid & 31;
    int gid  = lane >> 2;
    int tig  = lane & 3;
    int dir  = blockIdx.x >> 8;                 // block-uniform
    int wi   = (blockIdx.x & 255) * 2 + wb;     // 0..511

    const float* __restrict__ GI  = g_GI2 + dir * (VOC * G3);
    const float* __restrict__ bhh = dir ? bhh_b : bhh_f;

    // B fragments in registers (coalesced preload, reused for both tasks)
    unsigned bf[12][2][2];
    {
        const uint2* WF = g_WF + dir * 768;
        #pragma unroll
        for (int nb = 0; nb < 12; nb++)
            #pragma unroll
            for (int kc = 0; kc < 2; kc++) {
                uint2 v = WF[(nb * 2 + kc) * 32 + lane];
                bf[nb][kc][0] = v.x;
                bf[nb][kc][1] = v.y;
            }
    }
    float bn0 = bhh[64 + 2 * tig],      bn0b = bhh[64 + 2 * tig + 1];
    float bn1 = bhh[64 + 8 + 2 * tig],  bn1b = bhh[64 + 8 + 2 * tig + 1];
    float bn2 = bhh[64 + 16 + 2 * tig], bn2b = bhh[64 + 16 + 2 * tig + 1];
    float bn3 = bhh[64 + 24 + 2 * tig], bn3b = bhh[64 + 24 + 2 * tig + 1];

    #pragma unroll 1
    for (int task = 0; task < 2; task++) {
        int seq0 = (wi + task * 512) << 4;
        const int* xA = x + (seq0 + gid) * TCH;
        const int* xB = x + (seq0 + gid + 8) * TCH;

        float hn[4][4], hmax[4][4];
        #pragma unroll
        for (int hg = 0; hg < 4; hg++)
            #pragma unroll
            for (int s = 0; s < 4; s++) { hn[hg][s] = 0.0f; hmax[hg][s] = -CUDART_INF_F; }

        int t0 = dir ? (TCH - 1) : 0;
        int cA = xA[t0], cB = xB[t0];

        #pragma unroll 1
        for (int tt = 0; tt < TCH; ++tt) {
            int tn  = dir ? ((TCH - 2 - tt) & (TCH - 1)) : ((tt + 1) & (TCH - 1));
            int cAn = xA[tn], cBn = xB[tn];

            const float4* gA4 = (const float4*)(GI + cA * G3);
            const float4* gB4 = (const float4*)(GI + cB * G3);
            float4 ra0 = gA4[tig * 2],      ra1 = gA4[tig * 2 + 1];
            float4 za0 = gA4[8 + tig * 2],  za1 = gA4[8 + tig * 2 + 1];
            float4 na0 = gA4[16 + tig * 2], na1 = gA4[16 + tig * 2 + 1];
            float4 rb0 = gB4[tig * 2],      rb1 = gB4[tig * 2 + 1];
            float4 zb0 = gB4[8 + tig * 2],  zb1 = gB4[8 + tig * 2 + 1];
            float4 nb0 = gB4[16 + tig * 2], nb1 = gB4[16 + tig * 2 + 1];

            // D-layout h -> A fragments: LANE-LOCAL bf16 pack (no exchange!)
            // a[kc][0]: row gid,   k = 16kc+2tig,+1    -> hn[2kc][0..1]
            // a[kc][1]: row gid+8, same k              -> hn[2kc][2..3]
            // a[kc][2]: row gid,   k+8 (hg=2kc+1)      -> hn[2kc+1][0..1]
            // a[kc][3]: row gid+8                      -> hn[2kc+1][2..3]
            unsigned a[2][4];
            #pragma unroll
            for (int kc = 0; kc < 2; kc++) {
                a[kc][0] = packbf(hn[2 * kc][0],     hn[2 * kc][1]);
                a[kc][1] = packbf(hn[2 * kc][2],     hn[2 * kc][3]);
                a[kc][2] = packbf(hn[2 * kc + 1][0], hn[2 * kc + 1][1]);
                a[kc][3] = packbf(hn[2 * kc + 1][2], hn[2 * kc + 1][3]);
            }

            // accumulators: acc[nb][slot]; nb = gate*4 + hg
            float acc[12][4];
            acc[0][0]=ra0.x;  acc[0][1]=ra0.y;  acc[1][0]=ra0.z;  acc[1][1]=ra0.w;
            acc[2][0]=ra1.x;  acc[2][1]=ra1.y;  acc[3][0]=ra1.z;  acc[3][1]=ra1.w;
            acc[0][2]=rb0.x;  acc[0][3]=rb0.y;  acc[1][2]=rb0.z;  acc[1][3]=rb0.w;
            acc[2][2]=rb1.x;  acc[2][3]=rb1.y;  acc[3][2]=rb1.z;  acc[3][3]=rb1.w;
            acc[4][0]=za0.x;  acc[4][1]=za0.y;  acc[5][0]=za0.z;  acc[5][1]=za0.w;
            acc[6][0]=za1.x;  acc[6][1]=za1.y;  acc[7][0]=za1.z;  acc[7][1]=za1.w;
            acc[4][2]=zb0.x;  acc[4][3]=zb0.y;  acc[5][2]=zb0.z;  acc[5][3]=zb0.w;
            acc[6][2]=zb1.x;  acc[6][3]=zb1.y;  acc[7][2]=zb1.z;  acc[7][3]=zb1.w;
            acc[8][0]=bn0;  acc[8][1]=bn0b;  acc[9][0]=bn1;  acc[9][1]=bn1b;
            acc[10][0]=bn2; acc[10][1]=bn2b; acc[11][0]=bn3; acc[11][1]=bn3b;
            acc[8][2]=bn0;  acc[8][3]=bn0b;  acc[9][2]=bn1;  acc[9][3]=bn1b;
            acc[10][2]=bn2; acc[10][3]=bn2b; acc[11][2]=bn3; acc[11][3]=bn3b;

            float gin[4][4];
            gin[0][0]=na0.x; gin[0][1]=na0.y; gin[1][0]=na0.z; gin[1][1]=na0.w;
            gin[2][0]=na1.x; gin[2][1]=na1.y; gin[3][0]=na1.z; gin[3][1]=na1.w;
            gin[0][2]=nb0.x; gin[0][3]=nb0.y; gin[1][2]=nb0.z; gin[1][3]=nb0.w;
            gin[2][2]=nb1.x; gin[2][3]=nb1.y; gin[3][2]=nb1.z; gin[3][3]=nb1.w;

            #pragma unroll
            for (int kc = 0; kc < 2; kc++)
                #pragma unroll
                for (int nb = 0; nb < 12; nb++)
                    mma_bf16(acc[nb], a[kc], bf[nb][kc][0], bf[nb][kc][1]);

            // activations: r,z via sigmoid(x)=0.5+0.5*tanh(x/2) (prescaled)
            #pragma unroll
            for (int hg = 0; hg < 4; hg++)
                #pragma unroll
                for (int s = 0; s < 4; s++) {
                    float r = fmaf(tanhapx(acc[hg][s]),     0.5f, 0.5f);
                    float z = fmaf(tanhapx(acc[4 + hg][s]), 0.5f, 0.5f);
                    float n = tanhapx(fmaf(r, acc[8 + hg][s], gin[hg][s]));
                    float h = fmaf(z, hn[hg][s] - n, n);
                    hn[hg][s] = h;
                    hmax[hg][s] = fmaxf(hmax[hg][s], h);
                }

            cA = cAn; cB = cBn;
        }

        int sA = seq0 + gid, sB = seq0 + gid + 8;
        #pragma unroll
        for (int hg = 0; hg < 4; hg++) {
            int col = 8 * hg + 2 * tig;
            *(float2*)(out + sA * 64 + dir * 32 + col) = make_float2(hmax[hg][0], hmax[hg][1]);
            *(float2*)(out + sB * 64 + dir * 32 + col) = make_float2(hmax[hg][2], hmax[hg][3]);
        }
    }
}

// ---------------------------------------------------------------------------
// kernel_launch
// ---------------------------------------------------------------------------
extern "C" void kernel_launch(void* const* d_in, const int* in_sizes, int n_in,
                              void* d_out, int out_size) {
    const int*   x     = (const int*)  d_in[0];
    const float* emb   = (const float*)d_in[1];
    const float* Wih_f = (const float*)d_in[2];
    const float* Whh_f = (const float*)d_in[3];
    const float* bih_f = (const float*)d_in[4];
    const float* bhh_f = (const float*)d_in[5];
    const float* Wih_b = (const float*)d_in[6];
    const float* Whh_b = (const float*)d_in[7];
    const float* bih_b = (const float*)d_in[8];
    const float* bhh_b = (const float*)d_in[9];
    float* out = (float*)d_out;

    build_tables<<<VOC + 1, 192>>>(emb, Wih_f, bih_f, bhh_f,
                                   Wih_b, bih_b, bhh_b, Whh_f, Whh_b);

    // 512 blocks x 2 warps; each warp: 2 tasks of 16 seqs. Single wave.
    gru_mma<<<512, 64>>>(x, bhh_f, bhh_b, out);
}

// round 9
// speedup vs baseline: 4.3292x; 1.0964x over previous
#include <cuda_runtime.h>
#include <cuda_bf16.h>
#include <math_constants.h>

#define BATCH 64
#define SEQ   256
#define TCH   16
#define VOC   262
#define EMB   64
#define HID   32
#define G3    96
#define NSEQ  (BATCH*SEQ)

// Tables (device globals — no allocation allowed)
// Permuted GI rows: pos(gate,j) = gate*32 + tig*8 + hg*2 + e
// r,z entries pre-scaled by 0.5 (sigmoid-via-tanh); bhh folded for r,z.
__device__ __align__(128) float g_GI2[2 * VOC * G3];
// Pre-packed bf16 B fragments (m16n8k16): [dir][nb][kc][lane] = uint2(b0,b1)
// nb<8 rows pre-scaled 0.5.
__device__ uint2 g_WF[2 * 12 * 2 * 32];

__device__ __forceinline__ unsigned packbf(float lo, float hi) {
    unsigned d;
    asm("cvt.rn.bf16x2.f32 %0, %1, %2;" : "=r"(d) : "f"(hi), "f"(lo));
    return d;
}
__device__ __forceinline__ float tanhapx(float x) {
    float r;
    asm("tanh.approx.f32 %0, %1;" : "=f"(r) : "f"(x));
    return r;
}
__device__ __forceinline__ void mma_bf16(float* d, const unsigned* a,
                                         unsigned b0, unsigned b1) {
    asm("mma.sync.aligned.m16n8k16.row.col.f32.bf16.bf16.f32 "
        "{%0,%1,%2,%3}, {%4,%5,%6,%7}, {%8,%9}, {%0,%1,%2,%3};"
        : "+f"(d[0]), "+f"(d[1]), "+f"(d[2]), "+f"(d[3])
        : "r"(a[0]), "r"(a[1]), "r"(a[2]), "r"(a[3]),
          "r"(b0), "r"(b1));
}

// ---------------------------------------------------------------------------
// Kernel 1: GI tables + bf16 B-fragment pack. grid = VOC+1, block = 192.
// ---------------------------------------------------------------------------
__global__ void build_tables(const float* __restrict__ emb,
                             const float* __restrict__ Wih_f,
                             const float* __restrict__ bih_f,
                             const float* __restrict__ bhh_f,
                             const float* __restrict__ Wih_b,
                             const float* __restrict__ bih_b,
                             const float* __restrict__ bhh_b,
                             const float* __restrict__ Whh_f,
                             const float* __restrict__ Whh_b) {
    int c   = blockIdx.x;
    int tid = threadIdx.x;
    if (c < VOC) {
        int dir = tid / 96;
        int g   = tid % 96;
        __shared__ float e[EMB];
        if (tid < EMB) e[tid] = emb[c * EMB + tid];
        __syncthreads();
        const float* Wih = dir ? Wih_b : Wih_f;
        const float* bih = dir ? bih_b : bih_f;
        const float* bhh = dir ? bhh_b : bhh_f;
        float a0 = bih[g] + (g < 64 ? bhh[g] : 0.0f);
        float a1 = 0.0f;
        const float4* wr4 = (const float4*)(Wih + g * EMB);
        #pragma unroll
        for (int k4 = 0; k4 < EMB / 4; k4++) {
            float4 wv = wr4[k4];
            a0 = fmaf(wv.x, e[4 * k4],     a0);
            a1 = fmaf(wv.y, e[4 * k4 + 1], a1);
            a0 = fmaf(wv.z, e[4 * k4 + 2], a0);
            a1 = fmaf(wv.w, e[4 * k4 + 3], a1);
        }
        float v = a0 + a1;
        if (g < 64) v *= 0.5f;               // sigmoid-via-tanh prescale
        int gate = g >> 5, j = g & 31;
        int hg = j >> 3, tg = (j >> 1) & 3, eb = j & 1;
        int pos = gate * 32 + tg * 8 + hg * 2 + eb;
        g_GI2[dir * (VOC * G3) + c * G3 + pos] = v;
    } else {
        // pack bf16 B fragments (2*12*2*32 = 1536 uint2)
        for (int i = tid; i < 1536; i += 192) {
            int d    = i / 768;
            int rem  = i % 768;
            int nb   = rem / 64;
            int kc   = (rem / 32) & 1;
            int lane = rem & 31;
            int gid = lane >> 2, tg = lane & 3;
            const float* W = d ? Whh_b : Whh_f;
            const float* row = W + (8 * nb + gid) * HID;
            float s = (nb < 8) ? 0.5f : 1.0f;    // r,z rows prescaled
            int k0 = 16 * kc + 2 * tg;
            g_WF[i] = make_uint2(packbf(s * row[k0],     s * row[k0 + 1]),
                                 packbf(s * row[k0 + 8], s * row[k0 + 9]));
        }
    }
}

// ---------------------------------------------------------------------------
// Kernel 2: bf16 tensor-core GRU, software-pipelined gi loads.
// One warp = 16 sequences x 2 tasks, one dir. 24 bf16 m16n8k16 MMAs/step,
// lane-local D->A conversion, gi double-buffered one step ahead,
// char indices prefetched two steps ahead.
// ---------------------------------------------------------------------------
__global__ __launch_bounds__(64, 4)
void gru_mma(const int* __restrict__ x,
             const float* __restrict__ bhh_f,
             const float* __restrict__ bhh_b,
             float* __restrict__ out) {
    int tid  = threadIdx.x;
    int wb   = tid >> 5;
    int lane = tid & 31;
    int gid  = lane >> 2;
    int tig  = lane & 3;
    int dir  = blockIdx.x >> 8;                 // block-uniform
    int wi   = (blockIdx.x & 255) * 2 + wb;     // 0..511

    const float* __restrict__ GI  = g_GI2 + dir * (VOC * G3);
    const float* __restrict__ bhh = dir ? bhh_b : bhh_f;

    // B fragments in registers (reused for both tasks)
    unsigned bf[12][2][2];
    {
        const uint2* WF = g_WF + dir * 768;
        #pragma unroll
        for (int nb = 0; nb < 12; nb++)
            #pragma unroll
            for (int kc = 0; kc < 2; kc++) {
                uint2 v = WF[(nb * 2 + kc) * 32 + lane];
                bf[nb][kc][0] = v.x;
                bf[nb][kc][1] = v.y;
            }
    }
    float bn0 = bhh[64 + 2 * tig],      bn0b = bhh[64 + 2 * tig + 1];
    float bn1 = bhh[64 + 8 + 2 * tig],  bn1b = bhh[64 + 8 + 2 * tig + 1];
    float bn2 = bhh[64 + 16 + 2 * tig], bn2b = bhh[64 + 16 + 2 * tig + 1];
    float bn3 = bhh[64 + 24 + 2 * tig], bn3b = bhh[64 + 24 + 2 * tig + 1];

    #pragma unroll 1
    for (int task = 0; task < 2; task++) {
        int seq0 = (wi + task * 512) << 4;
        const int* xA = x + (seq0 + gid) * TCH;
        const int* xB = x + (seq0 + gid + 8) * TCH;

        float hn[4][4], hmax[4][4];
        #pragma unroll
        for (int hg = 0; hg < 4; hg++)
            #pragma unroll
            for (int s = 0; s < 4; s++) { hn[hg][s] = 0.0f; hmax[hg][s] = -CUDART_INF_F; }

        // step-index helpers: t(k) = dir ? 15-k : k
        int t0 = dir ? (TCH - 1) : 0;
        int t1 = dir ? (TCH - 2) : 1;
        int cA = xA[t0], cB = xB[t0];

        // gi for step 0 (current buffer)
        const float4* gA4 = (const float4*)(GI + cA * G3);
        const float4* gB4 = (const float4*)(GI + cB * G3);
        float4 ra0 = gA4[tig * 2],      ra1 = gA4[tig * 2 + 1];
        float4 za0 = gA4[8 + tig * 2],  za1 = gA4[8 + tig * 2 + 1];
        float4 na0 = gA4[16 + tig * 2], na1 = gA4[16 + tig * 2 + 1];
        float4 rb0 = gB4[tig * 2],      rb1 = gB4[tig * 2 + 1];
        float4 zb0 = gB4[8 + tig * 2],  zb1 = gB4[8 + tig * 2 + 1];
        float4 nb0 = gB4[16 + tig * 2], nb1 = gB4[16 + tig * 2 + 1];

        // char indices for step 1
        int cAn = xA[t1], cBn = xB[t1];

        #pragma unroll 1
        for (int tt = 0; tt < TCH; ++tt) {
            // --- prefetch: gi for step tt+1 (addresses ready in cAn/cBn) ---
            const float4* pA4 = (const float4*)(GI + cAn * G3);
            const float4* pB4 = (const float4*)(GI + cBn * G3);
            float4 pra0 = pA4[tig * 2],      pra1 = pA4[tig * 2 + 1];
            float4 pza0 = pA4[8 + tig * 2],  pza1 = pA4[8 + tig * 2 + 1];
            float4 pna0 = pA4[16 + tig * 2], pna1 = pA4[16 + tig * 2 + 1];
            float4 prb0 = pB4[tig * 2],      prb1 = pB4[tig * 2 + 1];
            float4 pzb0 = pB4[8 + tig * 2],  pzb1 = pB4[8 + tig * 2 + 1];
            float4 pnb0 = pB4[16 + tig * 2], pnb1 = pB4[16 + tig * 2 + 1];

            // --- prefetch: char indices for step tt+2 ---
            int tn2 = dir ? ((TCH - 3 - tt) & (TCH - 1)) : ((tt + 2) & (TCH - 1));
            cAn = xA[tn2];
            cBn = xB[tn2];

            // --- compute step tt from current registers ---
            unsigned a[2][4];
            #pragma unroll
            for (int kc = 0; kc < 2; kc++) {
                a[kc][0] = packbf(hn[2 * kc][0],     hn[2 * kc][1]);
                a[kc][1] = packbf(hn[2 * kc][2],     hn[2 * kc][3]);
                a[kc][2] = packbf(hn[2 * kc + 1][0], hn[2 * kc + 1][1]);
                a[kc][3] = packbf(hn[2 * kc + 1][2], hn[2 * kc + 1][3]);
            }

            float acc[12][4];
            acc[0][0]=ra0.x;  acc[0][1]=ra0.y;  acc[1][0]=ra0.z;  acc[1][1]=ra0.w;
            acc[2][0]=ra1.x;  acc[2][1]=ra1.y;  acc[3][0]=ra1.z;  acc[3][1]=ra1.w;
            acc[0][2]=rb0.x;  acc[0][3]=rb0.y;  acc[1][2]=rb0.z;  acc[1][3]=rb0.w;
            acc[2][2]=rb1.x;  acc[2][3]=rb1.y;  acc[3][2]=rb1.z;  acc[3][3]=rb1.w;
            acc[4][0]=za0.x;  acc[4][1]=za0.y;  acc[5][0]=za0.z;  acc[5][1]=za0.w;
            acc[6][0]=za1.x;  acc[6][1]=za1.y;  acc[7][0]=za1.z;  acc[7][1]=za1.w;
            acc[4][2]=zb0.x;  acc[4][3]=zb0.y;  acc[5][2]=zb0.z;  acc[5][3]=zb0.w;
            acc[6][2]=zb1.x;  acc[6][3]=zb1.y;  acc[7][2]=zb1.z;  acc[7][3]=zb1.w;
            acc[8][0]=bn0;  acc[8][1]=bn0b;  acc[9][0]=bn1;  acc[9][1]=bn1b;
            acc[10][0]=bn2; acc[10][1]=bn2b; acc[11][0]=bn3; acc[11][1]=bn3b;
            acc[8][2]=bn0;  acc[8][3]=bn0b;  acc[9][2]=bn1;  acc[9][3]=bn1b;
            acc[10][2]=bn2; acc[10][3]=bn2b; acc[11][2]=bn3; acc[11][3]=bn3b;

            float gin[4][4];
            gin[0][0]=na0.x; gin[0][1]=na0.y; gin[1][0]=na0.z; gin[1][1]=na0.w;
            gin[2][0]=na1.x; gin[2][1]=na1.y; gin[3][0]=na1.z; gin[3][1]=na1.w;
            gin[0][2]=nb0.x; gin[0][3]=nb0.y; gin[1][2]=nb0.z; gin[1][3]=nb0.w;
            gin[2][2]=nb1.x; gin[2][3]=nb1.y; gin[3][2]=nb1.z; gin[3][3]=nb1.w;

            #pragma unroll
            for (int kc = 0; kc < 2; kc++)
                #pragma unroll
                for (int nb = 0; nb < 12; nb++)
                    mma_bf16(acc[nb], a[kc], bf[nb][kc][0], bf[nb][kc][1]);

            #pragma unroll
            for (int hg = 0; hg < 4; hg++)
                #pragma unroll
                for (int s = 0; s < 4; s++) {
                    float r = fmaf(tanhapx(acc[hg][s]),     0.5f, 0.5f);
                    float z = fmaf(tanhapx(acc[4 + hg][s]), 0.5f, 0.5f);
                    float n = tanhapx(fmaf(r, acc[8 + hg][s], gin[hg][s]));
                    float h = fmaf(z, hn[hg][s] - n, n);
                    hn[hg][s] = h;
                    hmax[hg][s] = fmaxf(hmax[hg][s], h);
                }

            // rotate prefetch buffer into current
            ra0 = pra0; ra1 = pra1; za0 = pza0; za1 = pza1; na0 = pna0; na1 = pna1;
            rb0 = prb0; rb1 = prb1; zb0 = pzb0; zb1 = pzb1; nb0 = pnb0; nb1 = pnb1;
        }

        int sA = seq0 + gid, sB = seq0 + gid + 8;
        #pragma unroll
        for (int hg = 0; hg < 4; hg++) {
            int col = 8 * hg + 2 * tig;
            *(float2*)(out + sA * 64 + dir * 32 + col) = make_float2(hmax[hg][0], hmax[hg][1]);
            *(float2*)(out + sB * 64 + dir * 32 + col) = make_float2(hmax[hg][2], hmax[hg][3]);
        }
    }
}

// ---------------------------------------------------------------------------
// kernel_launch
// ---------------------------------------------------------------------------
extern "C" void kernel_launch(void* const* d_in, const int* in_sizes, int n_in,
                              void* d_out, int out_size) {
    const int*   x     = (const int*)  d_in[0];
    const float* emb   = (const float*)d_in[1];
    const float* Wih_f = (const float*)d_in[2];
    const float* Whh_f = (const float*)d_in[3];
    const float* bih_f = (const float*)d_in[4];
    const float* bhh_f = (const float*)d_in[5];
    const float* Wih_b = (const float*)d_in[6];
    const float* Whh_b = (const float*)d_in[7];
    const float* bih_b = (const float*)d_in[8];
    const float* bhh_b = (const float*)d_in[9];
    float* out = (float*)d_out;

    build_tables<<<VOC + 1, 192>>>(emb, Wih_f, bih_f, bhh_f,
                                   Wih_b, bih_b, bhh_b, Whh_f, Whh_b);

    // 512 blocks x 2 warps; each warp: 2 tasks of 16 seqs. Single wave.
    gru_mma<<<512, 64>>>(x, bhh_f, bhh_b, out);
}